// round 2
// baseline (speedup 1.0000x reference)
#include <cuda_runtime.h>
#include <cuda_bf16.h>
#include <cstdint>

// Problem constants
#define M_TOK 4096        // B*S tokens
#define N_OUT 4096
#define K_IN  4096
#define KTOT  (3 * K_IN)  // 12288: [x_hi|x_hi|x_lo] vs [w_hi|w_lo|w_hi]

// Scratch (allocation-free rule: static __device__ arrays)
__device__ __nv_bfloat16 g_A[(size_t)M_TOK * KTOT];  // 96 MB
__device__ __nv_bfloat16 g_W[(size_t)N_OUT * KTOT];  // 96 MB
__device__ int g_bases_is_i32;   // dtype detection flag

// ---------------------------------------------------------------------------
// Detect whether `bases` arrived as int32 or int8.
// If int32: first 16 int32 values are all exactly +1 or -1.
// If int8:  those 16 int32 words are 4 packed {0x01,0xFF} bytes each — the
//           chance all 16 decode to +/-1 is ~0.
// ---------------------------------------------------------------------------
__global__ void detect_bases_kernel(const int* __restrict__ bases) {
    if (threadIdx.x == 0 && blockIdx.x == 0) {
        int all_pm1 = 1;
        #pragma unroll
        for (int i = 0; i < 16; i++) {
            int v = bases[i];
            if (v != 1 && v != -1) { all_pm1 = 0; }
        }
        g_bases_is_i32 = all_pm1;
    }
}

// ---------------------------------------------------------------------------
// Prep: W' = concat_K [w_hi | w_lo | w_hi], w = sum_k alpha_k * base_k (+-1)
// Handles both int8 and int32 storage of `bases` via g_bases_is_i32.
// ---------------------------------------------------------------------------
__global__ void prep_w_kernel(const void* __restrict__ bases_raw,
                              const float* __restrict__ alphas) {
    int idx = blockIdx.x * blockDim.x + threadIdx.x;   // over 4096*4096/4
    const size_t plane = (size_t)N_OUT * K_IN;         // elements per k-plane
    float a0 = __ldg(alphas + 0), a1 = __ldg(alphas + 1);
    float a2 = __ldg(alphas + 2), a3 = __ldg(alphas + 3);

    float w[4];
    if (g_bases_is_i32) {
        const int* b = (const int*)bases_raw;
        int4 v0 = ((const int4*)(b))[idx];
        int4 v1 = ((const int4*)(b + plane))[idx];
        int4 v2 = ((const int4*)(b + 2 * plane))[idx];
        int4 v3 = ((const int4*)(b + 3 * plane))[idx];
        w[0] = a0 * (float)v0.x + a1 * (float)v1.x + a2 * (float)v2.x + a3 * (float)v3.x;
        w[1] = a0 * (float)v0.y + a1 * (float)v1.y + a2 * (float)v2.y + a3 * (float)v3.y;
        w[2] = a0 * (float)v0.z + a1 * (float)v1.z + a2 * (float)v2.z + a3 * (float)v3.z;
        w[3] = a0 * (float)v0.w + a1 * (float)v1.w + a2 * (float)v2.w + a3 * (float)v3.w;
    } else {
        const char* b = (const char*)bases_raw;
        char4 c0 = ((const char4*)(b))[idx];
        char4 c1 = ((const char4*)(b + plane))[idx];
        char4 c2 = ((const char4*)(b + 2 * plane))[idx];
        char4 c3 = ((const char4*)(b + 3 * plane))[idx];
        w[0] = a0 * (float)c0.x + a1 * (float)c1.x + a2 * (float)c2.x + a3 * (float)c3.x;
        w[1] = a0 * (float)c0.y + a1 * (float)c1.y + a2 * (float)c2.y + a3 * (float)c3.y;
        w[2] = a0 * (float)c0.z + a1 * (float)c1.z + a2 * (float)c2.z + a3 * (float)c3.z;
        w[3] = a0 * (float)c0.w + a1 * (float)c1.w + a2 * (float)c2.w + a3 * (float)c3.w;
    }

    union { __nv_bfloat162 b2[2]; uint2 u; } hv, lv;
    {
        __nv_bfloat16 h[4], l[4];
        #pragma unroll
        for (int e = 0; e < 4; e++) {
            h[e] = __float2bfloat16(w[e]);
            l[e] = __float2bfloat16(w[e] - __bfloat162float(h[e]));
        }
        hv.b2[0].x = h[0]; hv.b2[0].y = h[1]; hv.b2[1].x = h[2]; hv.b2[1].y = h[3];
        lv.b2[0].x = l[0]; lv.b2[0].y = l[1]; lv.b2[1].x = l[2]; lv.b2[1].y = l[3];
    }

    int o = (idx * 4) / K_IN;
    int i = (idx * 4) % K_IN;
    size_t base = (size_t)o * KTOT + i;
    *(uint2*)(g_W + base)            = hv.u;  // seg0: w_hi
    *(uint2*)(g_W + base + K_IN)     = lv.u;  // seg1: w_lo
    *(uint2*)(g_W + base + 2 * K_IN) = hv.u;  // seg2: w_hi
}

// ---------------------------------------------------------------------------
// Prep: A' = concat_K [x_hi | x_hi | x_lo]
// ---------------------------------------------------------------------------
__global__ void prep_x_kernel(const float* __restrict__ x) {
    int idx = blockIdx.x * blockDim.x + threadIdx.x;   // over 4096*4096/4
    float4 v = ((const float4*)x)[idx];
    float xv[4] = {v.x, v.y, v.z, v.w};

    union { __nv_bfloat162 b2[2]; uint2 u; } hv, lv;
    __nv_bfloat16 h[4], l[4];
    #pragma unroll
    for (int e = 0; e < 4; e++) {
        h[e] = __float2bfloat16(xv[e]);
        l[e] = __float2bfloat16(xv[e] - __bfloat162float(h[e]));
    }
    hv.b2[0].x = h[0]; hv.b2[0].y = h[1]; hv.b2[1].x = h[2]; hv.b2[1].y = h[3];
    lv.b2[0].x = l[0]; lv.b2[0].y = l[1]; lv.b2[1].x = l[2]; lv.b2[1].y = l[3];

    int m = (idx * 4) / K_IN;
    int i = (idx * 4) % K_IN;
    size_t base = (size_t)m * KTOT + i;
    *(uint2*)(g_A + base)            = hv.u;  // seg0: x_hi
    *(uint2*)(g_A + base + K_IN)     = hv.u;  // seg1: x_hi
    *(uint2*)(g_A + base + 2 * K_IN) = lv.u;  // seg2: x_lo
}

// ---------------------------------------------------------------------------
// GEMM: C[4096,4096] = A'[4096,12288] * W'^T, bf16 inputs, fp32 accumulate
// 128x128 CTA tile, BK=32, 8 warps (2x4), warp tile 64x32, mma.m16n8k16
// ---------------------------------------------------------------------------
#define BK 32
#define LDT 40            // padded smem row stride (conflict-free)
#define STAGE_BYTES (128 * LDT * 2)

__device__ __forceinline__ void cp_async16(uint32_t dst, const void* src) {
    asm volatile("cp.async.cg.shared.global [%0], [%1], 16;\n" :: "r"(dst), "l"(src));
}
__device__ __forceinline__ void cp_commit() {
    asm volatile("cp.async.commit_group;\n");
}
template <int N> __device__ __forceinline__ void cp_wait() {
    asm volatile("cp.async.wait_group %0;\n" :: "n"(N));
}
__device__ __forceinline__ void mma16816(float* c, const uint32_t* a, const uint32_t* b) {
    asm volatile(
        "mma.sync.aligned.m16n8k16.row.col.f32.bf16.bf16.f32 "
        "{%0,%1,%2,%3}, {%4,%5,%6,%7}, {%8,%9}, {%0,%1,%2,%3};\n"
        : "+f"(c[0]), "+f"(c[1]), "+f"(c[2]), "+f"(c[3])
        : "r"(a[0]), "r"(a[1]), "r"(a[2]), "r"(a[3]), "r"(b[0]), "r"(b[1]));
}

__global__ __launch_bounds__(256) void gemm_kernel(float* __restrict__ C) {
    __shared__ alignas(16) __nv_bfloat16 sA[2][128 * LDT];
    __shared__ alignas(16) __nv_bfloat16 sB[2][128 * LDT];

    const int tid = threadIdx.x;
    const int bm = blockIdx.y, bn = blockIdx.x;

    // Global load mapping: 256 threads cover 64 rows x 4 chunks(16B); two passes for 128 rows
    const int lrow = tid >> 2;            // 0..63
    const int lch  = (tid & 3) * 8;       // element offset of 16B chunk
    const __nv_bfloat16* gA0 = g_A + (size_t)(bm * 128 + lrow) * KTOT + lch;
    const __nv_bfloat16* gA1 = gA0 + (size_t)64 * KTOT;
    const __nv_bfloat16* gB0 = g_W + (size_t)(bn * 128 + lrow) * KTOT + lch;
    const __nv_bfloat16* gB1 = gB0 + (size_t)64 * KTOT;

    const uint32_t sA_base = (uint32_t)__cvta_generic_to_shared(&sA[0][0]);
    const uint32_t sB_base = (uint32_t)__cvta_generic_to_shared(&sB[0][0]);
    const uint32_t dOff = (uint32_t)(lrow * LDT + lch) * 2;

    const int NK = KTOT / BK;  // 384

    // warp layout
    const int warp = tid >> 5, lane = tid & 31;
    const int wm = warp & 1;       // 0..1  (64 rows each)
    const int wn = warp >> 1;      // 0..3  (32 cols each)
    const int g  = lane >> 2;      // 0..7
    const int tg = lane & 3;       // 0..3

    float acc[4][4][4];
    #pragma unroll
    for (int mi = 0; mi < 4; mi++)
        #pragma unroll
        for (int ni = 0; ni < 4; ni++)
            #pragma unroll
            for (int e = 0; e < 4; e++) acc[mi][ni][e] = 0.f;

    // prologue: stage 0
    {
        uint32_t a0 = sA_base + dOff;
        uint32_t b0 = sB_base + dOff;
        cp_async16(a0, gA0);
        cp_async16(a0 + 64 * LDT * 2, gA1);
        cp_async16(b0, gB0);
        cp_async16(b0 + 64 * LDT * 2, gB1);
        cp_commit();
    }

    for (int kt = 0; kt < NK; ++kt) {
        const int buf = kt & 1;
        if (kt + 1 < NK) {
            const int nb = (kt + 1) & 1;
            const size_t ko = (size_t)(kt + 1) * BK;
            uint32_t a0 = sA_base + nb * STAGE_BYTES + dOff;
            uint32_t b0 = sB_base + nb * STAGE_BYTES + dOff;
            cp_async16(a0, gA0 + ko);
            cp_async16(a0 + 64 * LDT * 2, gA1 + ko);
            cp_async16(b0, gB0 + ko);
            cp_async16(b0 + 64 * LDT * 2, gB1 + ko);
            cp_commit();
            cp_wait<1>();
        } else {
            cp_wait<0>();
        }
        __syncthreads();

        const __nv_bfloat16* tA = sA[buf];
        const __nv_bfloat16* tB = sB[buf];

        #pragma unroll
        for (int ks = 0; ks < BK; ks += 16) {
            uint32_t af[4][4], bf[4][2];
            #pragma unroll
            for (int mi = 0; mi < 4; mi++) {
                const int r = wm * 64 + mi * 16 + g;
                af[mi][0] = *(const uint32_t*)(tA + r * LDT + ks + tg * 2);
                af[mi][1] = *(const uint32_t*)(tA + (r + 8) * LDT + ks + tg * 2);
                af[mi][2] = *(const uint32_t*)(tA + r * LDT + ks + 8 + tg * 2);
                af[mi][3] = *(const uint32_t*)(tA + (r + 8) * LDT + ks + 8 + tg * 2);
            }
            #pragma unroll
            for (int ni = 0; ni < 4; ni++) {
                const int c = wn * 32 + ni * 8 + g;
                bf[ni][0] = *(const uint32_t*)(tB + c * LDT + ks + tg * 2);
                bf[ni][1] = *(const uint32_t*)(tB + c * LDT + ks + 8 + tg * 2);
            }
            #pragma unroll
            for (int mi = 0; mi < 4; mi++)
                #pragma unroll
                for (int ni = 0; ni < 4; ni++)
                    mma16816(acc[mi][ni], af[mi], bf[ni]);
        }
        __syncthreads();
    }

    // epilogue: fp32 stores
    #pragma unroll
    for (int mi = 0; mi < 4; mi++) {
        #pragma unroll
        for (int ni = 0; ni < 4; ni++) {
            const int row = bm * 128 + wm * 64 + mi * 16 + g;
            const int col = bn * 128 + wn * 32 + ni * 8 + tg * 2;
            *(float2*)(C + (size_t)row * N_OUT + col) =
                make_float2(acc[mi][ni][0], acc[mi][ni][1]);
            *(float2*)(C + (size_t)(row + 8) * N_OUT + col) =
                make_float2(acc[mi][ni][2], acc[mi][ni][3]);
        }
    }
}

// ---------------------------------------------------------------------------
extern "C" void kernel_launch(void* const* d_in, const int* in_sizes, int n_in,
                              void* d_out, int out_size) {
    // Identify inputs by element count (defensive against ordering)
    const float* x = nullptr;
    const float* alphas = nullptr;
    const void* bases = nullptr;
    for (int i = 0; i < n_in; i++) {
        if (in_sizes[i] == 4) alphas = (const float*)d_in[i];
        else if (in_sizes[i] == 16777216) x = (const float*)d_in[i];       // 2*2048*4096
        else if (in_sizes[i] == 67108864) bases = (const void*)d_in[i];    // 4*4096*4096
    }
    float* y = (float*)d_out;

    detect_bases_kernel<<<1, 32>>>((const int*)bases);

    const int prep_threads = 256;
    const int prep_blocks = (4096 * 4096 / 4) / prep_threads;  // 16384
    prep_w_kernel<<<prep_blocks, prep_threads>>>(bases, alphas);
    prep_x_kernel<<<prep_blocks, prep_threads>>>(x);

    dim3 grid(N_OUT / 128, M_TOK / 128);  // 32 x 32
    gemm_kernel<<<grid, 256>>>(y);
}

// round 4
// speedup vs baseline: 3.9758x; 3.9758x over previous
#include <cuda_runtime.h>
#include <cuda.h>
#include <cuda_bf16.h>
#include <cstdint>

// ---------------------------------------------------------------------------
// Problem: y[4096,4096] = x[4096,4096] @ W^T, W = sum_k alpha_k * bases_k
// 3-term bf16 split: y = x_hi W_hi + x_lo W_hi + x_hi W_lo  (fp32 accum)
// ---------------------------------------------------------------------------
#define M_TOK 4096
#define N_OUT 4096
#define K_IN  4096

// Arch-specific (sm_103a) feature detection at compile time, per pass.
#if defined(__CUDA_ARCH_FEAT_SM103_ALL) \
    || (defined(__CUDA_ARCH_SPECIFIC__) && (__CUDA_ARCH_SPECIFIC__ == 1030)) \
    || (defined(__CUDA_ARCH_FAMILY_SPECIFIC__) && (__CUDA_ARCH_FAMILY_SPECIFIC__ == 1030))
#define HAS_TC 1
#else
#define HAS_TC 0
#endif

// Scratch (static __device__ per allocation-free rule): 4 x 32MB bf16
__device__ __nv_bfloat16 g_Ah[(size_t)M_TOK * K_IN];
__device__ __nv_bfloat16 g_Al[(size_t)M_TOK * K_IN];
__device__ __nv_bfloat16 g_Wh[(size_t)N_OUT * K_IN];
__device__ __nv_bfloat16 g_Wl[(size_t)N_OUT * K_IN];
__device__ int g_bases_is_i32;
__device__ int g_has_tcgen05;

// ---------------------------------------------------------------------------
// Common PTX helpers (all non-arch-specific)
// ---------------------------------------------------------------------------
__device__ __forceinline__ uint32_t smem_to_u32(const void* p) {
    uint32_t a;
    asm("{ .reg .u64 t; cvta.to.shared.u64 t, %1; cvt.u32.u64 %0, t; }"
        : "=r"(a) : "l"(p));
    return a;
}
__device__ __forceinline__ void cp_async16(uint32_t dst, const void* src) {
    asm volatile("cp.async.cg.shared.global [%0], [%1], 16;\n" :: "r"(dst), "l"(src));
}
__device__ __forceinline__ void cp_commit() {
    asm volatile("cp.async.commit_group;\n");
}
template <int N> __device__ __forceinline__ void cp_wait() {
    asm volatile("cp.async.wait_group %0;\n" :: "n"(N));
}
__device__ __forceinline__ void ldsm4(uint32_t* r, uint32_t addr) {
    asm volatile("ldmatrix.sync.aligned.m8n8.x4.shared.b16 {%0,%1,%2,%3}, [%4];"
        : "=r"(r[0]), "=r"(r[1]), "=r"(r[2]), "=r"(r[3]) : "r"(addr));
}
__device__ __forceinline__ void mma16816(float* c, const uint32_t* a, const uint32_t* b) {
    asm volatile(
        "mma.sync.aligned.m16n8k16.row.col.f32.bf16.bf16.f32 "
        "{%0,%1,%2,%3}, {%4,%5,%6,%7}, {%8,%9}, {%0,%1,%2,%3};\n"
        : "+f"(c[0]), "+f"(c[1]), "+f"(c[2]), "+f"(c[3])
        : "r"(a[0]), "r"(a[1]), "r"(a[2]), "r"(a[3]), "r"(b[0]), "r"(b[1]));
}

#define MBARRIER_INIT(mbar, count) \
    asm volatile("mbarrier.init.shared.b64 [%0], %1;" \
        :: "r"((uint32_t)(mbar)), "r"((uint32_t)(count)) : "memory")
#define MBARRIER_EXPECT_TX(mbar, tx) \
    asm volatile("mbarrier.arrive.expect_tx.shared.b64 _, [%0], %1;" \
        :: "r"((uint32_t)(mbar)), "r"((uint32_t)(tx)) : "memory")
#define MBARRIER_WAIT_PARITY(mbar, parity) do { \
    uint32_t _m = (uint32_t)(mbar), _p = (uint32_t)(parity), _d; \
    asm volatile("{\n\t.reg .pred p;\n\t" \
        "mbarrier.try_wait.parity.acquire.cta.shared::cta.b64 p, [%1], %2;\n\t" \
        "selp.b32 %0, 1, 0, p;\n\t}" : "=r"(_d) : "r"(_m), "r"(_p) : "memory"); \
    if (!_d) { \
        asm volatile("{\n\t.reg .pred P1;\n\t" \
            "WL_%=:\n\t" \
            "mbarrier.try_wait.parity.acquire.cta.shared::cta.b64 P1, [%0], %1, 0x989680;\n\t" \
            "@P1 bra.uni WD_%=;\n\t" \
            "bra.uni WL_%=;\n\t" \
            "WD_%=:\n\t}" :: "r"(_m), "r"(_p) : "memory"); \
    } \
} while (0)
#define FENCE_PROXY_ASYNC_SHARED_CTA() \
    asm volatile("fence.proxy.async.shared::cta;" ::: "memory")

// ---------------------------------------------------------------------------
// Probe: report whether the *running* cubin was compiled with sm_103a features
// ---------------------------------------------------------------------------
__global__ void probe_kernel() {
    g_has_tcgen05 = HAS_TC;
}

// ---------------------------------------------------------------------------
// Detection: bases dtype (int8 vs int32) — values are all +/-1 iff int32
// ---------------------------------------------------------------------------
__global__ void detect_bases_kernel(const int* __restrict__ bases) {
    if (threadIdx.x == 0 && blockIdx.x == 0) {
        int all_pm1 = 1;
        #pragma unroll
        for (int i = 0; i < 16; i++) {
            int v = bases[i];
            if (v != 1 && v != -1) all_pm1 = 0;
        }
        g_bases_is_i32 = all_pm1;
    }
}

// ---------------------------------------------------------------------------
// Prep W: W = sum alpha_k * base_k; split W -> (W_hi, W_lo) bf16
// ---------------------------------------------------------------------------
__global__ void prep_w_kernel(const void* __restrict__ bases_raw,
                              const float* __restrict__ alphas) {
    int idx = blockIdx.x * blockDim.x + threadIdx.x;   // over 4096*4096/4
    const size_t plane = (size_t)N_OUT * K_IN;
    float a0 = __ldg(alphas + 0), a1 = __ldg(alphas + 1);
    float a2 = __ldg(alphas + 2), a3 = __ldg(alphas + 3);

    float w[4];
    if (g_bases_is_i32) {
        const int* b = (const int*)bases_raw;
        int4 v0 = ((const int4*)(b))[idx];
        int4 v1 = ((const int4*)(b + plane))[idx];
        int4 v2 = ((const int4*)(b + 2 * plane))[idx];
        int4 v3 = ((const int4*)(b + 3 * plane))[idx];
        w[0] = a0 * (float)v0.x + a1 * (float)v1.x + a2 * (float)v2.x + a3 * (float)v3.x;
        w[1] = a0 * (float)v0.y + a1 * (float)v1.y + a2 * (float)v2.y + a3 * (float)v3.y;
        w[2] = a0 * (float)v0.z + a1 * (float)v1.z + a2 * (float)v2.z + a3 * (float)v3.z;
        w[3] = a0 * (float)v0.w + a1 * (float)v1.w + a2 * (float)v2.w + a3 * (float)v3.w;
    } else {
        const char* b = (const char*)bases_raw;
        char4 c0 = ((const char4*)(b))[idx];
        char4 c1 = ((const char4*)(b + plane))[idx];
        char4 c2 = ((const char4*)(b + 2 * plane))[idx];
        char4 c3 = ((const char4*)(b + 3 * plane))[idx];
        w[0] = a0 * (float)c0.x + a1 * (float)c1.x + a2 * (float)c2.x + a3 * (float)c3.x;
        w[1] = a0 * (float)c0.y + a1 * (float)c1.y + a2 * (float)c2.y + a3 * (float)c3.y;
        w[2] = a0 * (float)c0.z + a1 * (float)c1.z + a2 * (float)c2.z + a3 * (float)c3.z;
        w[3] = a0 * (float)c0.w + a1 * (float)c1.w + a2 * (float)c2.w + a3 * (float)c3.w;
    }

    union { __nv_bfloat162 b2[2]; uint2 u; } hv, lv;
    __nv_bfloat16 h[4], l[4];
    #pragma unroll
    for (int e = 0; e < 4; e++) {
        h[e] = __float2bfloat16(w[e]);
        l[e] = __float2bfloat16(w[e] - __bfloat162float(h[e]));
    }
    hv.b2[0].x = h[0]; hv.b2[0].y = h[1]; hv.b2[1].x = h[2]; hv.b2[1].y = h[3];
    lv.b2[0].x = l[0]; lv.b2[0].y = l[1]; lv.b2[1].x = l[2]; lv.b2[1].y = l[3];

    *(uint2*)(g_Wh + (size_t)idx * 4) = hv.u;
    *(uint2*)(g_Wl + (size_t)idx * 4) = lv.u;
}

// ---------------------------------------------------------------------------
// Prep X: split x -> (x_hi, x_lo) bf16
// ---------------------------------------------------------------------------
__global__ void prep_x_kernel(const float* __restrict__ x) {
    int idx = blockIdx.x * blockDim.x + threadIdx.x;   // over 4096*4096/4
    float4 v = ((const float4*)x)[idx];
    float xv[4] = {v.x, v.y, v.z, v.w};

    union { __nv_bfloat162 b2[2]; uint2 u; } hv, lv;
    __nv_bfloat16 h[4], l[4];
    #pragma unroll
    for (int e = 0; e < 4; e++) {
        h[e] = __float2bfloat16(xv[e]);
        l[e] = __float2bfloat16(xv[e] - __bfloat162float(h[e]));
    }
    hv.b2[0].x = h[0]; hv.b2[0].y = h[1]; hv.b2[1].x = h[2]; hv.b2[1].y = h[3];
    lv.b2[0].x = l[0]; lv.b2[0].y = l[1]; lv.b2[1].x = l[2]; lv.b2[1].y = l[3];

    *(uint2*)(g_Ah + (size_t)idx * 4) = hv.u;
    *(uint2*)(g_Al + (size_t)idx * 4) = lv.u;
}

// ===========================================================================
// Path 1: HMMA (mma.sync) GEMM — always available.
// Fused 3-term: per K-chunk load Ah,Al,Bh,Bl fragments once, issue 3 MMAs.
// CTA tile 128x128, BK=32, 8 warps (2x4), warp tile 64x32, ldmatrix.x4.
// ===========================================================================
#define BKH 32
#define LDT 40                       // padded smem row stride (elements)
#define TILE_B (128 * LDT * 2)       // 10240 bytes per tensor tile
#define STG_B  (4 * TILE_B)          // 40960 bytes per stage
#define HMMA_SMEM (2 * STG_B)        // 81920

__global__ __launch_bounds__(256) void gemm_hmma(float* __restrict__ C) {
    if (g_has_tcgen05) return;       // tcgen05 path handles it

    extern __shared__ char smem[];
    const uint32_t sb = smem_to_u32(smem);
    const int tid = threadIdx.x;
    const int bm = blockIdx.y, bn = blockIdx.x;

    // global->smem mapping: 256 threads cover 64 rows x 4 chunks(16B)/tensor
    const int lrow = tid >> 2;
    const int lch  = (tid & 3) * 8;
    const __nv_bfloat16* gAh0 = g_Ah + (size_t)(bm * 128 + lrow) * K_IN + lch;
    const __nv_bfloat16* gAl0 = g_Al + (size_t)(bm * 128 + lrow) * K_IN + lch;
    const __nv_bfloat16* gBh0 = g_Wh + (size_t)(bn * 128 + lrow) * K_IN + lch;
    const __nv_bfloat16* gBl0 = g_Wl + (size_t)(bn * 128 + lrow) * K_IN + lch;
    const size_t half = (size_t)64 * K_IN;
    const uint32_t dOff = (uint32_t)(lrow * LDT + lch) * 2;
    const uint32_t hOff = 64 * LDT * 2;

    const int warp = tid >> 5, lane = tid & 31;
    const int wm = warp & 1;      // 0..1 (64 rows)
    const int wn = warp >> 1;     // 0..3 (32 cols)
    const int g  = lane >> 2;
    const int tg = lane & 3;

    // ldmatrix per-lane byte offsets within a tensor tile
    const uint32_t aoff =
        ((uint32_t)(wm * 64 + (lane & 7) + ((lane >> 3) & 1) * 8) * LDT
         + ((lane >> 4) & 1) * 8) * 2;
    const uint32_t boff =
        ((uint32_t)(wn * 32 + (lane & 7) + ((lane >> 4) & 1) * 8) * LDT
         + ((lane >> 3) & 1) * 8) * 2;

    float acc[4][4][4];
    #pragma unroll
    for (int mi = 0; mi < 4; mi++)
        #pragma unroll
        for (int ni = 0; ni < 4; ni++)
            #pragma unroll
            for (int e = 0; e < 4; e++) acc[mi][ni][e] = 0.f;

    const int NK = K_IN / BKH;    // 128

    // prologue: stage 0
    {
        uint32_t d = sb + dOff;
        cp_async16(d, gAh0);                       cp_async16(d + hOff, gAh0 + half);
        cp_async16(d + TILE_B, gAl0);              cp_async16(d + TILE_B + hOff, gAl0 + half);
        cp_async16(d + 2 * TILE_B, gBh0);          cp_async16(d + 2 * TILE_B + hOff, gBh0 + half);
        cp_async16(d + 3 * TILE_B, gBl0);          cp_async16(d + 3 * TILE_B + hOff, gBl0 + half);
        cp_commit();
    }

    for (int kt = 0; kt < NK; ++kt) {
        const int buf = kt & 1;
        if (kt + 1 < NK) {
            const int nb = (kt + 1) & 1;
            const size_t ko = (size_t)(kt + 1) * BKH;
            uint32_t d = sb + nb * STG_B + dOff;
            cp_async16(d, gAh0 + ko);              cp_async16(d + hOff, gAh0 + half + ko);
            cp_async16(d + TILE_B, gAl0 + ko);     cp_async16(d + TILE_B + hOff, gAl0 + half + ko);
            cp_async16(d + 2 * TILE_B, gBh0 + ko); cp_async16(d + 2 * TILE_B + hOff, gBh0 + half + ko);
            cp_async16(d + 3 * TILE_B, gBl0 + ko); cp_async16(d + 3 * TILE_B + hOff, gBl0 + half + ko);
            cp_commit();
            cp_wait<1>();
        } else {
            cp_wait<0>();
        }
        __syncthreads();

        const uint32_t base = sb + buf * STG_B;

        #pragma unroll
        for (int ks2 = 0; ks2 < 2; ks2++) {
            const uint32_t ko = ks2 * 32;   // 16 elems * 2B
            uint32_t ah[4][4], al[4][4], bh[2][4], bl[2][4];
            #pragma unroll
            for (int mi = 0; mi < 4; mi++)
                ldsm4(ah[mi], base + aoff + mi * (16 * LDT * 2) + ko);
            #pragma unroll
            for (int mi = 0; mi < 4; mi++)
                ldsm4(al[mi], base + TILE_B + aoff + mi * (16 * LDT * 2) + ko);
            #pragma unroll
            for (int nj = 0; nj < 2; nj++)
                ldsm4(bh[nj], base + 2 * TILE_B + boff + nj * (16 * LDT * 2) + ko);
            #pragma unroll
            for (int nj = 0; nj < 2; nj++)
                ldsm4(bl[nj], base + 3 * TILE_B + boff + nj * (16 * LDT * 2) + ko);

            #pragma unroll
            for (int mi = 0; mi < 4; mi++) {
                #pragma unroll
                for (int ni = 0; ni < 4; ni++) {
                    const uint32_t* bhp = &bh[ni >> 1][(ni & 1) * 2];
                    const uint32_t* blp = &bl[ni >> 1][(ni & 1) * 2];
                    mma16816(acc[mi][ni], ah[mi], bhp);
                    mma16816(acc[mi][ni], al[mi], bhp);
                    mma16816(acc[mi][ni], ah[mi], blp);
                }
            }
        }
        __syncthreads();
    }

    // epilogue
    #pragma unroll
    for (int mi = 0; mi < 4; mi++) {
        #pragma unroll
        for (int ni = 0; ni < 4; ni++) {
            const int row = bm * 128 + wm * 64 + mi * 16 + g;
            const int col = bn * 128 + wn * 32 + ni * 8 + tg * 2;
            *(float2*)(C + (size_t)row * N_OUT + col) =
                make_float2(acc[mi][ni][0], acc[mi][ni][1]);
            *(float2*)(C + (size_t)(row + 8) * N_OUT + col) =
                make_float2(acc[mi][ni][2], acc[mi][ni][3]);
        }
    }
}

// ===========================================================================
// Path 2: tcgen05 GEMM — compiled only in arch-specific (sm_103a) passes.
// CTA tile 128x256, BK=64, 2-stage TMA pipeline, TMEM fp32 accumulator.
// ===========================================================================
#define BM 128
#define BN 256
#define BK 64
#define NCHUNK (K_IN / BK)   // 64
#define STAGES 2
#define A_BYTES (BM * BK * 2)
#define B_BYTES (BN * BK * 2)
#define STG_BYTES (2 * A_BYTES + 2 * B_BYTES)
#define SM_TMA_FULL(s) ((s) * 8)
#define SM_MMA_DONE(s) (16 + (s) * 8)
#define SM_TMEM_PTR    32
#define SM_TILES       1024
#define SM_AH(s) (SM_TILES + (s) * STG_BYTES)
#define SM_AL(s) (SM_AH(s) + A_BYTES)
#define SM_BH(s) (SM_AL(s) + A_BYTES)
#define SM_BL(s) (SM_BH(s) + B_BYTES)
#define TC_SMEM (SM_TILES + STAGES * STG_BYTES)   // 197632
#define GEMM_IDESC ((1u << 4) | (1u << 7) | (1u << 10) | ((BN / 8) << 17) | ((BM / 16) << 24))

#if HAS_TC
static constexpr uint64_t SMEM_DESC_BASE_SW128 =
    (uint64_t(2) << 61) | (uint64_t(1) << 46) | (uint64_t(64) << 32) | (uint64_t(1) << 16);
#define MAKE_SMEM_DESC(addr) \
    (SMEM_DESC_BASE_SW128 | ((uint64_t)((addr) >> 4) & 0x3FFF))

__device__ __forceinline__ void mma_f16_ss(uint32_t d_tmem, uint64_t a_desc,
                                           uint64_t b_desc, uint32_t idesc,
                                           uint32_t enable) {
    asm volatile(
        "{\n\t.reg .pred p;\n\t"
        "setp.ne.u32 p, %5, 0;\n\t"
        "tcgen05.mma.cta_group::1.kind::f16 [%0], %1, %2, %3, {%4,%4,%4,%4}, p;\n\t}"
        :: "r"(d_tmem), "l"(a_desc), "l"(b_desc), "r"(idesc), "r"(0u), "r"(enable)
        : "memory");
}
__device__ __forceinline__ void tma_load_2d(uint32_t smem_addr,
                                            const CUtensorMap* tm,
                                            int x, int y, uint32_t mbar) {
    asm volatile(
        "cp.async.bulk.tensor.2d.shared::cta.global.tile.mbarrier::complete_tx::bytes "
        "[%0], [%1, {%2, %3}], [%4];"
        :: "r"(smem_addr), "l"(tm), "r"(x), "r"(y), "r"(mbar) : "memory");
}
#endif  // HAS_TC

__global__ __launch_bounds__(256, 1) void gemm_tc(
    float* __restrict__ C,
    const __grid_constant__ CUtensorMap tm_ah,
    const __grid_constant__ CUtensorMap tm_al,
    const __grid_constant__ CUtensorMap tm_bh,
    const __grid_constant__ CUtensorMap tm_bl) {
#if HAS_TC
    if (!g_has_tcgen05) return;
    extern __shared__ char smem[];
    const uint32_t sb = smem_to_u32(smem);
    const int tid = threadIdx.x;
    const int wid = tid >> 5, lane = tid & 31;
    const int bn = blockIdx.x, bm = blockIdx.y;

    if (tid == 0) {
        MBARRIER_INIT(sb + SM_TMA_FULL(0), 1);
        MBARRIER_INIT(sb + SM_TMA_FULL(1), 1);
        MBARRIER_INIT(sb + SM_MMA_DONE(0), 1);
        MBARRIER_INIT(sb + SM_MMA_DONE(1), 1);
        FENCE_PROXY_ASYNC_SHARED_CTA();
    }
    if (wid == 0) {
        asm volatile("tcgen05.alloc.cta_group::1.sync.aligned.shared::cta.b32 [%0], %1;"
            :: "r"(sb + SM_TMEM_PTR), "r"(256u) : "memory");
        asm volatile("tcgen05.relinquish_alloc_permit.cta_group::1.sync.aligned;");
    }
    __syncthreads();

    uint32_t tmem;
    asm volatile("ld.shared.b32 %0, [%1];" : "=r"(tmem) : "r"(sb + SM_TMEM_PTR));

    if (tid == 0) {
        #pragma unroll
        for (int p = 0; p < STAGES; p++) {
            MBARRIER_EXPECT_TX(sb + SM_TMA_FULL(p), STG_BYTES);
            const int kx = p * BK;
            tma_load_2d(sb + SM_AH(p), &tm_ah, kx, bm * BM, sb + SM_TMA_FULL(p));
            tma_load_2d(sb + SM_AL(p), &tm_al, kx, bm * BM, sb + SM_TMA_FULL(p));
            tma_load_2d(sb + SM_BH(p), &tm_bh, kx, bn * BN, sb + SM_TMA_FULL(p));
            tma_load_2d(sb + SM_BL(p), &tm_bl, kx, bn * BN, sb + SM_TMA_FULL(p));
        }
        for (int kt = 0; kt < NCHUNK; kt++) {
            const int s = kt & 1;
            const int ph = (kt >> 1) & 1;
            MBARRIER_WAIT_PARITY(sb + SM_TMA_FULL(s), ph);

            const uint64_t dah = MAKE_SMEM_DESC(sb + SM_AH(s));
            const uint64_t dal = MAKE_SMEM_DESC(sb + SM_AL(s));
            const uint64_t dbh = MAKE_SMEM_DESC(sb + SM_BH(s));
            const uint64_t dbl = MAKE_SMEM_DESC(sb + SM_BL(s));
            #pragma unroll
            for (int ks = 0; ks < 4; ks++) {
                const uint64_t o = (uint64_t)(ks * 2);
                mma_f16_ss(tmem, dah + o, dbh + o, GEMM_IDESC, !(kt == 0 && ks == 0));
                mma_f16_ss(tmem, dal + o, dbh + o, GEMM_IDESC, 1u);
                mma_f16_ss(tmem, dah + o, dbl + o, GEMM_IDESC, 1u);
            }
            asm volatile(
                "tcgen05.commit.cta_group::1.mbarrier::arrive::one.shared::cluster.b64 [%0];"
                :: "r"(sb + SM_MMA_DONE(s)) : "memory");

            if (kt + STAGES < NCHUNK) {
                MBARRIER_WAIT_PARITY(sb + SM_MMA_DONE(s), ph);
                MBARRIER_EXPECT_TX(sb + SM_TMA_FULL(s), STG_BYTES);
                const int kx = (kt + STAGES) * BK;
                tma_load_2d(sb + SM_AH(s), &tm_ah, kx, bm * BM, sb + SM_TMA_FULL(s));
                tma_load_2d(sb + SM_AL(s), &tm_al, kx, bm * BM, sb + SM_TMA_FULL(s));
                tma_load_2d(sb + SM_BH(s), &tm_bh, kx, bn * BN, sb + SM_TMA_FULL(s));
                tma_load_2d(sb + SM_BL(s), &tm_bl, kx, bn * BN, sb + SM_TMA_FULL(s));
            }
        }
        MBARRIER_WAIT_PARITY(sb + SM_MMA_DONE((NCHUNK - 1) & 1), ((NCHUNK - 1) >> 1) & 1);
        asm volatile("tcgen05.fence::before_thread_sync;" ::: "memory");
    }
    __syncthreads();

    if (tid < 128) {
        asm volatile("tcgen05.fence::after_thread_sync;" ::: "memory");
        const size_t row = (size_t)(bm * BM + wid * 32 + lane);
        float* crow = C + row * N_OUT + bn * BN;
        #pragma unroll
        for (int base = 0; base < BN; base += 32) {
            uint32_t d[32];
            asm volatile("tcgen05.ld.sync.aligned.32x32b.x32.b32 "
                "{%0,%1,%2,%3,%4,%5,%6,%7,%8,%9,%10,%11,%12,%13,%14,%15,"
                "%16,%17,%18,%19,%20,%21,%22,%23,%24,%25,%26,%27,%28,%29,%30,%31}, [%32];"
                : "=r"(d[0]), "=r"(d[1]), "=r"(d[2]), "=r"(d[3]),
                  "=r"(d[4]), "=r"(d[5]), "=r"(d[6]), "=r"(d[7]),
                  "=r"(d[8]), "=r"(d[9]), "=r"(d[10]), "=r"(d[11]),
                  "=r"(d[12]), "=r"(d[13]), "=r"(d[14]), "=r"(d[15]),
                  "=r"(d[16]), "=r"(d[17]), "=r"(d[18]), "=r"(d[19]),
                  "=r"(d[20]), "=r"(d[21]), "=r"(d[22]), "=r"(d[23]),
                  "=r"(d[24]), "=r"(d[25]), "=r"(d[26]), "=r"(d[27]),
                  "=r"(d[28]), "=r"(d[29]), "=r"(d[30]), "=r"(d[31])
                : "r"(tmem + base));
            asm volatile("tcgen05.wait::ld.sync.aligned;" ::: "memory");
            #pragma unroll
            for (int j = 0; j < 8; j++) {
                float4 v;
                v.x = __uint_as_float(d[4 * j + 0]);
                v.y = __uint_as_float(d[4 * j + 1]);
                v.z = __uint_as_float(d[4 * j + 2]);
                v.w = __uint_as_float(d[4 * j + 3]);
                *(float4*)(crow + base + 4 * j) = v;
            }
        }
    }
    __syncthreads();
    if (wid == 0) {
        asm volatile("tcgen05.dealloc.cta_group::1.sync.aligned.b32 %0, %1;"
            :: "r"(tmem), "r"(256u));
    }
#endif  // HAS_TC
}

// ---------------------------------------------------------------------------
// Host
// ---------------------------------------------------------------------------
typedef CUresult (*encode_fn_t)(
    CUtensorMap*, CUtensorMapDataType, cuuint32_t, void*,
    const cuuint64_t*, const cuuint64_t*, const cuuint32_t*, const cuuint32_t*,
    CUtensorMapInterleave, CUtensorMapSwizzle, CUtensorMapL2promotion,
    CUtensorMapFloatOOBfill);

static void encode_map(encode_fn_t fn, CUtensorMap* tm, void* base,
                       int rows, uint32_t box_rows) {
    if (!fn) return;
    cuuint64_t dims[2] = {(cuuint64_t)K_IN, (cuuint64_t)rows};
    cuuint64_t strides[1] = {(cuuint64_t)K_IN * 2};
    cuuint32_t box[2] = {(cuuint32_t)BK, box_rows};
    cuuint32_t es[2] = {1, 1};
    fn(tm, CU_TENSOR_MAP_DATA_TYPE_BFLOAT16, 2, base, dims, strides, box, es,
       CU_TENSOR_MAP_INTERLEAVE_NONE, CU_TENSOR_MAP_SWIZZLE_128B,
       CU_TENSOR_MAP_L2_PROMOTION_L2_128B, CU_TENSOR_MAP_FLOAT_OOB_FILL_NONE);
}

extern "C" void kernel_launch(void* const* d_in, const int* in_sizes, int n_in,
                              void* d_out, int out_size) {
    const float* x = nullptr;
    const float* alphas = nullptr;
    const void* bases = nullptr;
    for (int i = 0; i < n_in; i++) {
        if (in_sizes[i] == 4) alphas = (const float*)d_in[i];
        else if (in_sizes[i] == 16777216) x = (const float*)d_in[i];
        else if (in_sizes[i] == 67108864) bases = (const void*)d_in[i];
    }
    float* y = (float*)d_out;

    void* fnp = nullptr;
    cudaDriverEntryPointQueryResult qst;
#if CUDART_VERSION >= 12050
    cudaGetDriverEntryPointByVersion("cuTensorMapEncodeTiled", &fnp, 12000,
                                     cudaEnableDefault, &qst);
#else
    cudaGetDriverEntryPoint("cuTensorMapEncodeTiled", &fnp, cudaEnableDefault, &qst);
#endif
    encode_fn_t enc = (encode_fn_t)fnp;

    void *pAh, *pAl, *pWh, *pWl;
    cudaGetSymbolAddress(&pAh, g_Ah);
    cudaGetSymbolAddress(&pAl, g_Al);
    cudaGetSymbolAddress(&pWh, g_Wh);
    cudaGetSymbolAddress(&pWl, g_Wl);

    CUtensorMap tm_ah = {}, tm_al = {}, tm_bh = {}, tm_bl = {};
    encode_map(enc, &tm_ah, pAh, M_TOK, BM);
    encode_map(enc, &tm_al, pAl, M_TOK, BM);
    encode_map(enc, &tm_bh, pWh, N_OUT, BN);
    encode_map(enc, &tm_bl, pWl, N_OUT, BN);

    cudaFuncSetAttribute(gemm_hmma,
                         cudaFuncAttributeMaxDynamicSharedMemorySize, HMMA_SMEM);
    cudaFuncSetAttribute(gemm_tc,
                         cudaFuncAttributeMaxDynamicSharedMemorySize, TC_SMEM);

    probe_kernel<<<1, 1>>>();
    detect_bases_kernel<<<1, 32>>>((const int*)bases);

    const int prep_threads = 256;
    const int prep_blocks = (4096 * 4096 / 4) / prep_threads;
    prep_w_kernel<<<prep_blocks, prep_threads>>>(bases, alphas);
    prep_x_kernel<<<prep_blocks, prep_threads>>>(x);

    dim3 grid_tc(N_OUT / BN, M_TOK / BM);       // 16 x 32
    gemm_tc<<<grid_tc, 256, TC_SMEM>>>(y, tm_ah, tm_al, tm_bh, tm_bl);

    dim3 grid_h(N_OUT / 128, M_TOK / 128);      // 32 x 32
    gemm_hmma<<<grid_h, 256, HMMA_SMEM>>>(y);
}